// round 7
// baseline (speedup 1.0000x reference)
#include <cuda_runtime.h>
#include <math.h>

#define D_MODEL 1024
#define D_STATE 16
#define D_INNER 2048
#define BATCH   2
#define SEQ     4096
#define NTOK    (BATCH*SEQ)
#define NCHUNK  16

// ---------------- scratch ----------------
__device__ __align__(16) float g_Ppart[NCHUNK * 32 * 1024]; // [chunk][o][d]
__device__ __align__(16) float g_MTp[4 * 16 * 1024];        // [quarter][n][d]
__device__ __align__(16) float g_Pp[1024 * 32];             // [d][o]
__device__ __align__(16) float g_MT[16 * 1024];             // [n][d]
__device__ float g_c[32];
__device__ float g_k1[32];
__device__ float g_k2[32];
__device__ __align__(16) float g_au[BATCH * 32 * SEQ];      // [b][o][s]
__device__ __align__(16) float g_states[BATCH * 16 * SEQ];  // [b*16+n][s]

__device__ __forceinline__ unsigned long long dup_f(float v) {
    unsigned long long r;
    asm("mov.b64 %0, {%1, %1};" : "=l"(r) : "f"(v));
    return r;
}
__device__ __forceinline__ unsigned long long pack2(float a, float b) {
    unsigned long long r;
    asm("mov.b64 %0, {%1, %2};" : "=l"(r) : "f"(a), "f"(b));
    return r;
}
__device__ __forceinline__ void cp16(unsigned int dst, const void* src) {
    asm volatile("cp.async.ca.shared.global [%0], [%1], 16;" :: "r"(dst), "l"(src));
}

// ---------------- K1: merged prologue (unchanged) ----------------
__global__ void __launch_bounds__(256) k_pm(const float* __restrict__ Win,
                                            const float* __restrict__ A,
                                            const float* __restrict__ Bs,
                                            const float* __restrict__ Wout,
                                            const float* __restrict__ C,
                                            const float* __restrict__ b_in) {
    int blk = blockIdx.x;
    int tid = threadIdx.x;

    if (blk < 64) {
        __shared__ __align__(16) unsigned long long sAB2[128 * 32];
        int dt = blk >> 4;
        int chunk = blk & 15;
        int e0 = chunk * 128;
        for (int i = tid; i < 128 * 16; i += 256) {
            int el = i >> 4, n = i & 15;
            sAB2[el * 32 + n]      = dup_f(A [(e0 + el) * 16 + n]);
            sAB2[el * 32 + 16 + n] = dup_f(Bs[(e0 + el) * 16 + n]);
        }
        __syncthreads();
        int dp = tid >> 1, oh = tid & 1;
        int d = dt * 256 + dp * 2;
        unsigned long long acc[16];
#pragma unroll
        for (int o = 0; o < 16; o++) acc[o] = 0ull;
#pragma unroll 4
        for (int el = 0; el < 128; el++) {
            unsigned long long w01 = *(const unsigned long long*)(Win + (e0 + el) * 1024 + d);
            const unsigned long long* base = sAB2 + el * 32 + oh * 16;
#pragma unroll
            for (int o = 0; o < 16; o++)
                asm("fma.rn.f32x2 %0, %1, %2, %0;" : "+l"(acc[o]) : "l"(w01), "l"(base[o]));
        }
#pragma unroll
        for (int o = 0; o < 16; o++) {
            int oi = oh * 16 + o;
            *(unsigned long long*)(g_Ppart + (chunk * 32 + oi) * 1024 + d) = acc[o];
        }
        return;
    }

    if (blk < 128) {
        __shared__ __align__(16) float sC[128 * 16];
        int mb = blk - 64;
        int tile = mb >> 2;
        int q = mb & 3;
        int row = tile * 64 + (tid >> 2);
        int nq = tid & 3;
        unsigned long long acc0 = 0ull, acc1 = 0ull;
        for (int c = 0; c < 4; c++) {
            int e0 = q * 512 + c * 128;
            __syncthreads();
            for (int i = tid; i < 512; i += 256)
                ((float4*)sC)[i] = ((const float4*)(C + e0 * 16))[i];
            __syncthreads();
            const float* wrow = Wout + row * 2048 + e0;
#pragma unroll 8
            for (int g = 0; g < 32; g++) {
                float4 w4 = *(const float4*)(wrow + g * 4);
#pragma unroll
                for (int j = 0; j < 4; j++) {
                    float wv = (j == 0) ? w4.x : (j == 1) ? w4.y : (j == 2) ? w4.z : w4.w;
                    unsigned long long wd = dup_f(wv);
                    ulonglong2 cp = *(const ulonglong2*)(sC + (g * 4 + j) * 16 + nq * 4);
                    asm("fma.rn.f32x2 %0, %1, %2, %0;" : "+l"(acc0) : "l"(wd), "l"(cp.x));
                    asm("fma.rn.f32x2 %0, %1, %2, %0;" : "+l"(acc1) : "l"(wd), "l"(cp.y));
                }
            }
        }
        float a[4];
        asm("mov.b64 {%0, %1}, %2;" : "=f"(a[0]), "=f"(a[1]) : "l"(acc0));
        asm("mov.b64 {%0, %1}, %2;" : "=f"(a[2]), "=f"(a[3]) : "l"(acc1));
#pragma unroll
        for (int i = 0; i < 4; i++) {
            int n = nq * 4 + i;
            g_MTp[(q * 16 + n) * 1024 + row] = a[i];
        }
        return;
    }

    {
        __shared__ float red[8 * 16];
        int lane = tid & 31, w = tid >> 5;
        const float* G = (blk == 128) ? A : Bs;
        float acc[16];
#pragma unroll
        for (int n = 0; n < 16; n++) acc[n] = 0.f;
        for (int e = tid; e < 2048; e += 256) {
            float bv = b_in[e];
            const float4* g4 = (const float4*)(G + e * 16);
            float4 c0 = g4[0], c1 = g4[1], c2 = g4[2], c3 = g4[3];
            acc[0] += bv * c0.x; acc[1] += bv * c0.y; acc[2] += bv * c0.z; acc[3] += bv * c0.w;
            acc[4] += bv * c1.x; acc[5] += bv * c1.y; acc[6] += bv * c1.z; acc[7] += bv * c1.w;
            acc[8] += bv * c2.x; acc[9] += bv * c2.y; acc[10]+= bv * c2.z; acc[11]+= bv * c2.w;
            acc[12]+= bv * c3.x; acc[13]+= bv * c3.y; acc[14]+= bv * c3.z; acc[15]+= bv * c3.w;
        }
#pragma unroll
        for (int off = 16; off; off >>= 1)
#pragma unroll
            for (int n = 0; n < 16; n++) acc[n] += __shfl_down_sync(0xffffffffu, acc[n], off);
        if (lane == 0) {
#pragma unroll
            for (int n = 0; n < 16; n++) red[w * 16 + n] = acc[n];
        }
        __syncthreads();
        if (tid < 16) {
            float s = 0.f;
#pragma unroll
            for (int j = 0; j < 8; j++) s += red[j * 16 + tid];
            if (blk == 128) g_c[tid] = s; else g_c[16 + tid] = s;
        }
    }
}

// ---------------- K2: fold (unchanged) ----------------
__global__ void k_fold(const float* __restrict__ nw, const float* __restrict__ nb) {
    int blk = blockIdx.x;
    int tid = threadIdx.x;
    if (blk >= 32) {
        int tile = blk - 32;
        for (int i = tid; i < 1024; i += 256) {
            int d = tile * 64 + (i >> 4), n = i & 15;
            float s = 0.f;
#pragma unroll
            for (int q = 0; q < 4; q++) s += g_MTp[(q * 16 + n) * 1024 + d];
            g_MT[n * 1024 + d] = s;
        }
        return;
    }
    int o = blk;
    int lane = tid & 31, w = tid >> 5;
    float s1 = 0.f, s2 = 0.f;
    for (int d = tid; d < 1024; d += 256) {
        float p = 0.f;
#pragma unroll
        for (int c = 0; c < NCHUNK; c++) p += g_Ppart[(c * 32 + o) * 1024 + d];
        float wn = nw[d];
        s1 += wn * p;
        s2 += nb[d] * p;
        g_Pp[d * 32 + o] = wn * p;
    }
#pragma unroll
    for (int off = 16; off; off >>= 1) {
        s1 += __shfl_down_sync(0xffffffffu, s1, off);
        s2 += __shfl_down_sync(0xffffffffu, s2, off);
    }
    __shared__ float r1[8], r2[8];
    if (lane == 0) { r1[w] = s1; r2[w] = s2; }
    __syncthreads();
    if (tid == 0) {
        float t1 = 0.f, t2 = 0.f;
#pragma unroll
        for (int j = 0; j < 8; j++) { t1 += r1[j]; t2 += r2[j]; }
        g_k1[o] = t1;
        g_k2[o] = t2 + g_c[o];
    }
}

// ---------------- K3: fused LN+projection, 2-tokens-per-f32x2-lane ----------------
// grid 128 blocks (64 tokens) x 256 threads.
// thread: pair p = tid>>3 (tokens 2p, 2p+1), oq = tid&7 (outputs oq*4..oq*4+3)
#define XROW 36                       // padded floats per token row (16B-aligned stride)
#define XBUF (64 * XROW)              // per-buffer x floats (9216 -> 36KB total? 2*9216*4=73KB NO)
// x per buffer: 64 rows x 36 = 2304 floats = 9.2KB; 2 bufs = 18.4KB. P dup: 32k x 64 = 2048 fl = 8.2KB x2 = 16.4KB. Total 34.8KB OK.
#define PDBUF (32 * 64)
__global__ void __launch_bounds__(256) k_ln(const float* __restrict__ x) {
    __shared__ __align__(16) float sX[2 * XBUF];
    __shared__ __align__(16) float sPd[2 * PDBUF];
    int tid = threadIdx.x;
    int t0 = blockIdx.x * 64;
    int p = tid >> 3;                 // 0..31
    int oq = tid & 7;                 // 0..7
    int pr = tid >> 3;                // P-row within chunk (0..31)
    int pq = tid & 7;                 // P float4 col (0..7)

    unsigned int sxb = (unsigned int)__cvta_generic_to_shared(sX);

    auto load_x = [&](int c, int buf) {
#pragma unroll
        for (int it = 0; it < 2; it++) {
            int idx = tid + it * 256;
            int r = idx >> 3, cx = idx & 7;   // 64 rows x 8 float4
            cp16(sxb + (buf * XBUF + r * XROW + cx * 4) * 4,
                 x + (t0 + r) * 1024 + c * 32 + cx * 4);
        }
        asm volatile("cp.async.commit_group;");
    };
    auto store_pdup = [&](float4 v, int buf) {
        float* dst = sPd + buf * PDBUF + pr * 64 + pq * 8;
        *(float4*)(dst)     = make_float4(v.x, v.x, v.y, v.y);
        *(float4*)(dst + 4) = make_float4(v.z, v.z, v.w, v.w);
    };

    // prologue: chunk 0
    load_x(0, 0);
    float4 pv = *(const float4*)(g_Pp + pr * 32 + pq * 4);
    store_pdup(pv, 0);
    asm volatile("cp.async.wait_group 0;");
    __syncthreads();

    unsigned long long a0 = 0, a1 = 0, a2 = 0, a3 = 0;
    unsigned long long s1x = 0, s2x = 0;

    for (int c = 0; c < 32; c++) {
        int buf = c & 1;
        if (c < 31) {
            pv = *(const float4*)(g_Pp + ((c + 1) * 32 + pr) * 32 + pq * 4);
            load_x(c + 1, buf ^ 1);
        }
        const float* xr = sX + buf * XBUF + (2 * p) * XROW;
        const float* Pb = sPd + buf * PDBUF + oq * 8;
#pragma unroll
        for (int k = 0; k < 32; k++) {
            float x0 = xr[k];
            float x1 = xr[XROW + k];
            unsigned long long xx = pack2(x0, x1);
            ulonglong2 pA = *(const ulonglong2*)(Pb + k * 64);
            ulonglong2 pB = *(const ulonglong2*)(Pb + k * 64 + 4);
            asm("fma.rn.f32x2 %0, %1, %2, %0;" : "+l"(a0) : "l"(xx), "l"(pA.x));
            asm("fma.rn.f32x2 %0, %1, %2, %0;" : "+l"(a1) : "l"(xx), "l"(pA.y));
            asm("fma.rn.f32x2 %0, %1, %2, %0;" : "+l"(a2) : "l"(xx), "l"(pB.x));
            asm("fma.rn.f32x2 %0, %1, %2, %0;" : "+l"(a3) : "l"(xx), "l"(pB.y));
            asm("add.rn.f32x2 %0, %0, %1;" : "+l"(s1x) : "l"(xx));
            asm("fma.rn.f32x2 %0, %1, %1, %0;" : "+l"(s2x) : "l"(xx));
        }
        if (c < 31) {
            store_pdup(pv, buf ^ 1);
            asm volatile("cp.async.wait_group 0;");
        }
        __syncthreads();
    }

    float v0[4], v1[4];
    asm("mov.b64 {%0, %1}, %2;" : "=f"(v0[0]), "=f"(v1[0]) : "l"(a0));
    asm("mov.b64 {%0, %1}, %2;" : "=f"(v0[1]), "=f"(v1[1]) : "l"(a1));
    asm("mov.b64 {%0, %1}, %2;" : "=f"(v0[2]), "=f"(v1[2]) : "l"(a2));
    asm("mov.b64 {%0, %1}, %2;" : "=f"(v0[3]), "=f"(v1[3]) : "l"(a3));
    float s1_0, s1_1, s2_0, s2_1;
    asm("mov.b64 {%0, %1}, %2;" : "=f"(s1_0), "=f"(s1_1) : "l"(s1x));
    asm("mov.b64 {%0, %1}, %2;" : "=f"(s2_0), "=f"(s2_1) : "l"(s2x));

    float mu0 = s1_0 * (1.f / 1024.f);
    float mu1 = s1_1 * (1.f / 1024.f);
    float rs0 = rsqrtf(s2_0 * (1.f / 1024.f) - mu0 * mu0 + 1e-5f);
    float rs1 = rsqrtf(s2_1 * (1.f / 1024.f) - mu1 * mu1 + 1e-5f);

    int tg = t0 + 2 * p;
    int b = tg >> 12, s = tg & 4095;
#pragma unroll
    for (int i = 0; i < 4; i++) {
        int o = oq * 4 + i;
        float k1v = g_k1[o], k2v = g_k2[o];
        float val0 = rs0 * v0[i] - mu0 * rs0 * k1v + k2v;
        float val1 = rs1 * v1[i] - mu1 * rs1 * k1v + k2v;
        if (o < 16) {
            val0 = 1.f / (1.f + __expf(-val0));
            val1 = 1.f / (1.f + __expf(-val1));
        }
        *(unsigned long long*)(g_au + (b * 32 + o) * 4096 + s) = pack2(val0, val1);
    }
}

// ---------------- K4: 32 parallel scans (unchanged) ----------------
__global__ void __launch_bounds__(512) k_scan() {
    int bn = blockIdx.x;
    int b = bn >> 4, n = bn & 15;
    const float* ap = g_au + (b * 32 + n) * 4096;
    const float* up = g_au + (b * 32 + 16 + n) * 4096;
    int tid = threadIdx.x;
    int lane = tid & 31, w = tid >> 5;

    float a[8], u[8];
    const float4* a4 = (const float4*)(ap + tid * 8);
    const float4* u4 = (const float4*)(up + tid * 8);
#pragma unroll
    for (int q = 0; q < 2; q++) {
        float4 av = a4[q], uv = u4[q];
        a[q*4+0] = av.x; a[q*4+1] = av.y; a[q*4+2] = av.z; a[q*4+3] = av.w;
        u[q*4+0] = uv.x; u[q*4+1] = uv.y; u[q*4+2] = uv.z; u[q*4+3] = uv.w;
    }
    float Aloc = 1.f, Uloc = 0.f;
#pragma unroll
    for (int i = 0; i < 8; i++) { Uloc = Uloc * a[i] + u[i]; Aloc *= a[i]; }

    float Ai = Aloc, Ui = Uloc;
#pragma unroll
    for (int off = 1; off < 32; off <<= 1) {
        float Ap = __shfl_up_sync(0xffffffffu, Ai, off);
        float Up = __shfl_up_sync(0xffffffffu, Ui, off);
        if (lane >= off) { Ui = Up * Ai + Ui; Ai = Ap * Ai; }
    }
    __shared__ float wA[16], wU[16], pU[16];
    if (lane == 31) { wA[w] = Ai; wU[w] = Ui; }
    __syncthreads();
    if (tid == 0) {
        float Uc = 0.f;
#pragma unroll
        for (int j = 0; j < 16; j++) {
            pU[j] = Uc;
            Uc = Uc * wA[j] + wU[j];
        }
    }
    __syncthreads();
    float eA = __shfl_up_sync(0xffffffffu, Ai, 1);
    float eU = __shfl_up_sync(0xffffffffu, Ui, 1);
    if (lane == 0) { eA = 1.f; eU = 0.f; }
    float s = pU[w] * eA + eU;

    float out[8];
#pragma unroll
    for (int i = 0; i < 8; i++) { s = a[i] * s + u[i]; out[i] = s; }
    float4* dst = (float4*)(g_states + bn * 4096 + tid * 8);
#pragma unroll
    for (int q = 0; q < 2; q++)
        dst[q] = make_float4(out[q*4+0], out[q*4+1], out[q*4+2], out[q*4+3]);
}

// ---------------- K5: out = x + b_out + states @ MT  (f32x2, unchanged) ----------------
__global__ void __launch_bounds__(256) k_out(const float* __restrict__ x,
                                             const float* __restrict__ bo,
                                             float* __restrict__ out) {
    __shared__ float sST[32 * 17];
    int tid = threadIdx.x;
    int t0 = blockIdx.x * 32;
    int b = t0 >> 12, s0 = t0 & 4095;

#pragma unroll
    for (int it = 0; it < 2; it++) {
        int idx = tid + it * 256;
        int n = idx >> 5, soff = idx & 31;
        sST[soff * 17 + n] = g_states[(b * 16 + n) * 4096 + s0 + soff];
    }
    unsigned long long m01[16], m23[16];
#pragma unroll
    for (int n = 0; n < 16; n++) {
        ulonglong2 mm = *(const ulonglong2*)(g_MT + n * 1024 + tid * 4);
        m01[n] = mm.x; m23[n] = mm.y;
    }
    ulonglong2 bov = *(const ulonglong2*)((const float*)bo + tid * 4);
    __syncthreads();

    for (int t = 0; t < 32; t++) {
        ulonglong2 xv = *(const ulonglong2*)(x + (t0 + t) * 1024 + tid * 4);
        unsigned long long r01, r23;
        asm("add.rn.f32x2 %0, %1, %2;" : "=l"(r01) : "l"(xv.x), "l"(bov.x));
        asm("add.rn.f32x2 %0, %1, %2;" : "=l"(r23) : "l"(xv.y), "l"(bov.y));
#pragma unroll
        for (int n = 0; n < 16; n++) {
            unsigned long long sv = dup_f(sST[t * 17 + n]);
            asm("fma.rn.f32x2 %0, %1, %2, %0;" : "+l"(r01) : "l"(sv), "l"(m01[n]));
            asm("fma.rn.f32x2 %0, %1, %2, %0;" : "+l"(r23) : "l"(sv), "l"(m23[n]));
        }
        ulonglong2 res; res.x = r01; res.y = r23;
        *(ulonglong2*)(out + (t0 + t) * 1024 + tid * 4) = res;
    }
}

// ---------------- launch ----------------
extern "C" void kernel_launch(void* const* d_in, const int* in_sizes, int n_in,
                              void* d_out, int out_size) {
    const float* x    = (const float*)d_in[0];
    const float* nw   = (const float*)d_in[1];
    const float* nb   = (const float*)d_in[2];
    const float* Win  = (const float*)d_in[3];
    const float* b_in = (const float*)d_in[4];
    const float* A    = (const float*)d_in[5];
    const float* Bs   = (const float*)d_in[6];
    const float* C    = (const float*)d_in[7];
    const float* Wout = (const float*)d_in[8];
    const float* bo   = (const float*)d_in[9];
    float* out = (float*)d_out;

    k_pm  <<<130, 256>>>(Win, A, Bs, Wout, C, b_in);
    k_fold<<<48, 256>>>(nw, nb);
    k_ln  <<<128, 256>>>(x);
    k_scan<<<32, 512>>>();
    k_out <<<256, 256>>>(x, bo, out);
}

// round 8
// speedup vs baseline: 1.3803x; 1.3803x over previous
#include <cuda_runtime.h>
#include <math.h>

#define D_MODEL 1024
#define D_STATE 16
#define D_INNER 2048
#define BATCH   2
#define SEQ     4096
#define NTOK    (BATCH*SEQ)
#define NCHUNK  16

// ---------------- scratch ----------------
__device__ __align__(16) float g_Ppart[NCHUNK * 32 * 1024]; // [chunk][o][d]
__device__ __align__(16) float g_MTp[4 * 16 * 1024];        // [quarter][n][d]
__device__ __align__(16) float g_Pp[1024 * 32];             // [d][o]
__device__ __align__(16) float g_MT[16 * 1024];             // [n][d]
__device__ float g_c[32];
__device__ float g_k1[32];
__device__ float g_k2[32];
__device__ __align__(16) float g_au[BATCH * 32 * SEQ];      // [b][o][s]
__device__ __align__(16) float g_states[BATCH * 16 * SEQ];  // [b*16+n][s]

__device__ __forceinline__ unsigned long long dup_f(float v) {
    unsigned long long r;
    asm("mov.b64 %0, {%1, %1};" : "=l"(r) : "f"(v));
    return r;
}

// ---------------- K1: merged prologue (unchanged from R6) ----------------
__global__ void __launch_bounds__(256) k_pm(const float* __restrict__ Win,
                                            const float* __restrict__ A,
                                            const float* __restrict__ Bs,
                                            const float* __restrict__ Wout,
                                            const float* __restrict__ C,
                                            const float* __restrict__ b_in) {
    int blk = blockIdx.x;
    int tid = threadIdx.x;

    if (blk < 64) {
        __shared__ __align__(16) unsigned long long sAB2[128 * 32];
        int dt = blk >> 4;
        int chunk = blk & 15;
        int e0 = chunk * 128;
        for (int i = tid; i < 128 * 16; i += 256) {
            int el = i >> 4, n = i & 15;
            sAB2[el * 32 + n]      = dup_f(A [(e0 + el) * 16 + n]);
            sAB2[el * 32 + 16 + n] = dup_f(Bs[(e0 + el) * 16 + n]);
        }
        __syncthreads();
        int dp = tid >> 1, oh = tid & 1;
        int d = dt * 256 + dp * 2;
        unsigned long long acc[16];
#pragma unroll
        for (int o = 0; o < 16; o++) acc[o] = 0ull;
#pragma unroll 4
        for (int el = 0; el < 128; el++) {
            unsigned long long w01 = *(const unsigned long long*)(Win + (e0 + el) * 1024 + d);
            const unsigned long long* base = sAB2 + el * 32 + oh * 16;
#pragma unroll
            for (int o = 0; o < 16; o++)
                asm("fma.rn.f32x2 %0, %1, %2, %0;" : "+l"(acc[o]) : "l"(w01), "l"(base[o]));
        }
#pragma unroll
        for (int o = 0; o < 16; o++) {
            int oi = oh * 16 + o;
            *(unsigned long long*)(g_Ppart + (chunk * 32 + oi) * 1024 + d) = acc[o];
        }
        return;
    }

    if (blk < 128) {
        __shared__ __align__(16) float sC[128 * 16];
        int mb = blk - 64;
        int tile = mb >> 2;
        int q = mb & 3;
        int row = tile * 64 + (tid >> 2);
        int nq = tid & 3;
        unsigned long long acc0 = 0ull, acc1 = 0ull;
        for (int c = 0; c < 4; c++) {
            int e0 = q * 512 + c * 128;
            __syncthreads();
            for (int i = tid; i < 512; i += 256)
                ((float4*)sC)[i] = ((const float4*)(C + e0 * 16))[i];
            __syncthreads();
            const float* wrow = Wout + row * 2048 + e0;
#pragma unroll 8
            for (int g = 0; g < 32; g++) {
                float4 w4 = *(const float4*)(wrow + g * 4);
#pragma unroll
                for (int j = 0; j < 4; j++) {
                    float wv = (j == 0) ? w4.x : (j == 1) ? w4.y : (j == 2) ? w4.z : w4.w;
                    unsigned long long wd = dup_f(wv);
                    ulonglong2 cp = *(const ulonglong2*)(sC + (g * 4 + j) * 16 + nq * 4);
                    asm("fma.rn.f32x2 %0, %1, %2, %0;" : "+l"(acc0) : "l"(wd), "l"(cp.x));
                    asm("fma.rn.f32x2 %0, %1, %2, %0;" : "+l"(acc1) : "l"(wd), "l"(cp.y));
                }
            }
        }
        float a[4];
        asm("mov.b64 {%0, %1}, %2;" : "=f"(a[0]), "=f"(a[1]) : "l"(acc0));
        asm("mov.b64 {%0, %1}, %2;" : "=f"(a[2]), "=f"(a[3]) : "l"(acc1));
#pragma unroll
        for (int i = 0; i < 4; i++) {
            int n = nq * 4 + i;
            g_MTp[(q * 16 + n) * 1024 + row] = a[i];
        }
        return;
    }

    {
        __shared__ float red[8 * 16];
        int lane = tid & 31, w = tid >> 5;
        const float* G = (blk == 128) ? A : Bs;
        float acc[16];
#pragma unroll
        for (int n = 0; n < 16; n++) acc[n] = 0.f;
        for (int e = tid; e < 2048; e += 256) {
            float bv = b_in[e];
            const float4* g4 = (const float4*)(G + e * 16);
            float4 c0 = g4[0], c1 = g4[1], c2 = g4[2], c3 = g4[3];
            acc[0] += bv * c0.x; acc[1] += bv * c0.y; acc[2] += bv * c0.z; acc[3] += bv * c0.w;
            acc[4] += bv * c1.x; acc[5] += bv * c1.y; acc[6] += bv * c1.z; acc[7] += bv * c1.w;
            acc[8] += bv * c2.x; acc[9] += bv * c2.y; acc[10]+= bv * c2.z; acc[11]+= bv * c2.w;
            acc[12]+= bv * c3.x; acc[13]+= bv * c3.y; acc[14]+= bv * c3.z; acc[15]+= bv * c3.w;
        }
#pragma unroll
        for (int off = 16; off; off >>= 1)
#pragma unroll
            for (int n = 0; n < 16; n++) acc[n] += __shfl_down_sync(0xffffffffu, acc[n], off);
        if (lane == 0) {
#pragma unroll
            for (int n = 0; n < 16; n++) red[w * 16 + n] = acc[n];
        }
        __syncthreads();
        if (tid < 16) {
            float s = 0.f;
#pragma unroll
            for (int j = 0; j < 8; j++) s += red[j * 16 + tid];
            if (blk == 128) g_c[tid] = s; else g_c[16 + tid] = s;
        }
    }
}

// ---------------- K2: fold (unchanged) ----------------
__global__ void k_fold(const float* __restrict__ nw, const float* __restrict__ nb) {
    int blk = blockIdx.x;
    int tid = threadIdx.x;
    if (blk >= 32) {
        int tile = blk - 32;
        for (int i = tid; i < 1024; i += 256) {
            int d = tile * 64 + (i >> 4), n = i & 15;
            float s = 0.f;
#pragma unroll
            for (int q = 0; q < 4; q++) s += g_MTp[(q * 16 + n) * 1024 + d];
            g_MT[n * 1024 + d] = s;
        }
        return;
    }
    int o = blk;
    int lane = tid & 31, w = tid >> 5;
    float s1 = 0.f, s2 = 0.f;
    for (int d = tid; d < 1024; d += 256) {
        float p = 0.f;
#pragma unroll
        for (int c = 0; c < NCHUNK; c++) p += g_Ppart[(c * 32 + o) * 1024 + d];
        float wn = nw[d];
        s1 += wn * p;
        s2 += nb[d] * p;
        g_Pp[d * 32 + o] = wn * p;
    }
#pragma unroll
    for (int off = 16; off; off >>= 1) {
        s1 += __shfl_down_sync(0xffffffffu, s1, off);
        s2 += __shfl_down_sync(0xffffffffu, s2, off);
    }
    __shared__ float r1[8], r2[8];
    if (lane == 0) { r1[w] = s1; r2[w] = s2; }
    __syncthreads();
    if (tid == 0) {
        float t1 = 0.f, t2 = 0.f;
#pragma unroll
        for (int j = 0; j < 8; j++) { t1 += r1[j]; t2 += r2[j]; }
        g_k1[o] = t1;
        g_k2[o] = t2 + g_c[o];
    }
}

// ---------------- K3: LN + projection, 4x4 register tile, transposed x ----------------
// grid 128 blocks (64 tokens) x 256 threads.
// thread = (tg = tid&15 -> tokens tg*4..+3, og = (tid>>4)&7 -> outputs og*4..+3, ks = tid>>7)
#define XROWF 68   // floats per k-row of sXT (64 tokens + pad)
#define PROWF 36   // floats per k-row of sP  (32 outputs + pad)
__global__ void __launch_bounds__(256) k_ln(const float* __restrict__ x) {
    __shared__ __align__(16) float sXT[2][32 * XROWF];  // [k][t]  17.4KB
    __shared__ __align__(16) float sP [2][32 * PROWF];  // [k][o]   9.2KB
    __shared__ float sMu[64], sRs[64];
    __shared__ __align__(16) float sCmb[128 * 16];      // 8KB
    int tid = threadIdx.x;
    int T0 = blockIdx.x * 64;
    int lane = tid & 31, w = tid >> 5;

    // ---- phase 1: LN stats (coalesced, 8 warps x 8 tokens) ----
#pragma unroll
    for (int tk = 0; tk < 8; tk++) {
        int t = w * 8 + tk;
        const float4* xr = (const float4*)(x + (T0 + t) * 1024);
        float s1 = 0.f, s2 = 0.f;
#pragma unroll
        for (int q = 0; q < 8; q++) {
            float4 v = xr[lane + q * 32];
            s1 += v.x + v.y + v.z + v.w;
            s2 += v.x * v.x + v.y * v.y + v.z * v.z + v.w * v.w;
        }
#pragma unroll
        for (int off = 16; off; off >>= 1) {
            s1 += __shfl_down_sync(0xffffffffu, s1, off);
            s2 += __shfl_down_sync(0xffffffffu, s2, off);
        }
        if (lane == 0) {
            float mu = s1 * (1.f / 1024.f);
            float var = s2 * (1.f / 1024.f) - mu * mu;
            sMu[t] = mu;
            sRs[t] = rsqrtf(var + 1e-5f);
        }
    }

    // ---- phase 2: tiled GEMM ----
    int tg = tid & 15;
    int og = (tid >> 4) & 7;
    int ks = tid >> 7;

    // loader indices (x transpose): 2 iters cover 32k x 16 token-groups
    int lk0 = tid & 31;            // k within chunk
    int ltq0 = tid >> 5;           // token-group 0..7  (it adds +8)
    // P loader: 1 iter covers 32k x 8 o-groups
    int pk = tid >> 3;             // 0..31
    int po4 = tid & 7;             // 0..7

    float acc[16];
#pragma unroll
    for (int i = 0; i < 16; i++) acc[i] = 0.f;

    // prologue: load chunk 0 directly to smem
    {
#pragma unroll
        for (int it = 0; it < 2; it++) {
            int tq = ltq0 + it * 8;
            const float* xb = x + (T0 + tq * 4) * 1024 + lk0;
            float a0 = xb[0], a1 = xb[1024], a2 = xb[2048], a3 = xb[3072];
            *(float4*)&sXT[0][lk0 * XROWF + tq * 4] = make_float4(a0, a1, a2, a3);
        }
        float4 pv = *(const float4*)(g_Pp + pk * 32 + po4 * 4);
        *(float4*)&sP[0][pk * PROWF + po4 * 4] = pv;
    }
    __syncthreads();

    for (int c = 0; c < 32; c++) {
        int buf = c & 1;
        float a[2][4];
        float4 pv;
        if (c < 31) {   // prefetch chunk c+1 into registers (LDG overlapped w/ compute)
#pragma unroll
            for (int it = 0; it < 2; it++) {
                int tq = ltq0 + it * 8;
                const float* xb = x + (T0 + tq * 4) * 1024 + (c + 1) * 32 + lk0;
                a[it][0] = xb[0]; a[it][1] = xb[1024]; a[it][2] = xb[2048]; a[it][3] = xb[3072];
            }
            pv = *(const float4*)(g_Pp + (((c + 1) * 32) + pk) * 32 + po4 * 4);
        }

        const float* xbuf = &sXT[buf][ks * 16 * XROWF + tg * 4];
        const float* pbuf = &sP[buf][ks * 16 * PROWF + og * 4];
#pragma unroll
        for (int k = 0; k < 16; k++) {
            float4 xv = *(const float4*)(xbuf + k * XROWF);
            float4 pw = *(const float4*)(pbuf + k * PROWF);
            acc[0]  += xv.x * pw.x; acc[1]  += xv.x * pw.y; acc[2]  += xv.x * pw.z; acc[3]  += xv.x * pw.w;
            acc[4]  += xv.y * pw.x; acc[5]  += xv.y * pw.y; acc[6]  += xv.y * pw.z; acc[7]  += xv.y * pw.w;
            acc[8]  += xv.z * pw.x; acc[9]  += xv.z * pw.y; acc[10] += xv.z * pw.z; acc[11] += xv.z * pw.w;
            acc[12] += xv.w * pw.x; acc[13] += xv.w * pw.y; acc[14] += xv.w * pw.z; acc[15] += xv.w * pw.w;
        }

        if (c < 31) {
#pragma unroll
            for (int it = 0; it < 2; it++) {
                int tq = ltq0 + it * 8;
                *(float4*)&sXT[buf ^ 1][lk0 * XROWF + tq * 4] =
                    make_float4(a[it][0], a[it][1], a[it][2], a[it][3]);
            }
            *(float4*)&sP[buf ^ 1][pk * PROWF + po4 * 4] = pv;
        }
        __syncthreads();
    }

    // ---- combine k-split halves ----
    if (ks == 1) {
#pragma unroll
        for (int i = 0; i < 4; i++)
            *(float4*)&sCmb[(tid - 128) * 16 + i * 4] =
                make_float4(acc[i * 4], acc[i * 4 + 1], acc[i * 4 + 2], acc[i * 4 + 3]);
    }
    __syncthreads();
    if (ks == 0) {
#pragma unroll
        for (int i = 0; i < 4; i++) {
            float4 v = *(const float4*)&sCmb[tid * 16 + i * 4];
            acc[i * 4] += v.x; acc[i * 4 + 1] += v.y; acc[i * 4 + 2] += v.z; acc[i * 4 + 3] += v.w;
        }
        int tglob = T0 + tg * 4;
        int b = tglob >> 12, s0 = tglob & 4095;
        float mu[4], rs[4];
#pragma unroll
        for (int j = 0; j < 4; j++) { mu[j] = sMu[tg * 4 + j]; rs[j] = sRs[tg * 4 + j]; }
#pragma unroll
        for (int i = 0; i < 4; i++) {
            int o = og * 4 + i;
            float k1v = g_k1[o], k2v = g_k2[o];
            float vj[4];
#pragma unroll
            for (int j = 0; j < 4; j++) {
                float val = rs[j] * acc[j * 4 + i] - mu[j] * rs[j] * k1v + k2v;
                if (o < 16) val = 1.f / (1.f + __expf(-val));
                vj[j] = val;
            }
            *(float4*)(g_au + (b * 32 + o) * 4096 + s0) = make_float4(vj[0], vj[1], vj[2], vj[3]);
        }
    }
}

// ---------------- K4: 32 parallel scans (unchanged) ----------------
__global__ void __launch_bounds__(512) k_scan() {
    int bn = blockIdx.x;
    int b = bn >> 4, n = bn & 15;
    const float* ap = g_au + (b * 32 + n) * 4096;
    const float* up = g_au + (b * 32 + 16 + n) * 4096;
    int tid = threadIdx.x;
    int lane = tid & 31, w = tid >> 5;

    float a[8], u[8];
    const float4* a4 = (const float4*)(ap + tid * 8);
    const float4* u4 = (const float4*)(up + tid * 8);
#pragma unroll
    for (int q = 0; q < 2; q++) {
        float4 av = a4[q], uv = u4[q];
        a[q*4+0] = av.x; a[q*4+1] = av.y; a[q*4+2] = av.z; a[q*4+3] = av.w;
        u[q*4+0] = uv.x; u[q*4+1] = uv.y; u[q*4+2] = uv.z; u[q*4+3] = uv.w;
    }
    float Aloc = 1.f, Uloc = 0.f;
#pragma unroll
    for (int i = 0; i < 8; i++) { Uloc = Uloc * a[i] + u[i]; Aloc *= a[i]; }

    float Ai = Aloc, Ui = Uloc;
#pragma unroll
    for (int off = 1; off < 32; off <<= 1) {
        float Ap = __shfl_up_sync(0xffffffffu, Ai, off);
        float Up = __shfl_up_sync(0xffffffffu, Ui, off);
        if (lane >= off) { Ui = Up * Ai + Ui; Ai = Ap * Ai; }
    }
    __shared__ float wA[16], wU[16], pU[16];
    if (lane == 31) { wA[w] = Ai; wU[w] = Ui; }
    __syncthreads();
    if (tid == 0) {
        float Uc = 0.f;
#pragma unroll
        for (int j = 0; j < 16; j++) {
            pU[j] = Uc;
            Uc = Uc * wA[j] + wU[j];
        }
    }
    __syncthreads();
    float eA = __shfl_up_sync(0xffffffffu, Ai, 1);
    float eU = __shfl_up_sync(0xffffffffu, Ui, 1);
    if (lane == 0) { eA = 1.f; eU = 0.f; }
    float s = pU[w] * eA + eU;

    float out[8];
#pragma unroll
    for (int i = 0; i < 8; i++) { s = a[i] * s + u[i]; out[i] = s; }
    float4* dst = (float4*)(g_states + bn * 4096 + tid * 8);
#pragma unroll
    for (int q = 0; q < 2; q++)
        dst[q] = make_float4(out[q*4+0], out[q*4+1], out[q*4+2], out[q*4+3]);
}

// ---------------- K5: out = x + b_out + states @ MT (unchanged) ----------------
__global__ void __launch_bounds__(256) k_out(const float* __restrict__ x,
                                             const float* __restrict__ bo,
                                             float* __restrict__ out) {
    __shared__ float sST[32 * 17];
    int tid = threadIdx.x;
    int t0 = blockIdx.x * 32;
    int b = t0 >> 12, s0 = t0 & 4095;

#pragma unroll
    for (int it = 0; it < 2; it++) {
        int idx = tid + it * 256;
        int n = idx >> 5, soff = idx & 31;
        sST[soff * 17 + n] = g_states[(b * 16 + n) * 4096 + s0 + soff];
    }
    unsigned long long m01[16], m23[16];
#pragma unroll
    for (int n = 0; n < 16; n++) {
        ulonglong2 mm = *(const ulonglong2*)(g_MT + n * 1024 + tid * 4);
        m01[n] = mm.x; m23[n] = mm.y;
    }
    ulonglong2 bov = *(const ulonglong2*)((const float*)bo + tid * 4);
    __syncthreads();

    for (int t = 0; t < 32; t++) {
        ulonglong2 xv = *(const ulonglong2*)(x + (t0 + t) * 1024 + tid * 4);
        unsigned long long r01, r23;
        asm("add.rn.f32x2 %0, %1, %2;" : "=l"(r01) : "l"(xv.x), "l"(bov.x));
        asm("add.rn.f32x2 %0, %1, %2;" : "=l"(r23) : "l"(xv.y), "l"(bov.y));
#pragma unroll
        for (int n = 0; n < 16; n++) {
            unsigned long long sv = dup_f(sST[t * 17 + n]);
            asm("fma.rn.f32x2 %0, %1, %2, %0;" : "+l"(r01) : "l"(sv), "l"(m01[n]));
            asm("fma.rn.f32x2 %0, %1, %2, %0;" : "+l"(r23) : "l"(sv), "l"(m23[n]));
        }
        ulonglong2 res; res.x = r01; res.y = r23;
        *(ulonglong2*)(out + (t0 + t) * 1024 + tid * 4) = res;
    }
}

// ---------------- launch ----------------
extern "C" void kernel_launch(void* const* d_in, const int* in_sizes, int n_in,
                              void* d_out, int out_size) {
    const float* x    = (const float*)d_in[0];
    const float* nw   = (const float*)d_in[1];
    const float* nb   = (const float*)d_in[2];
    const float* Win  = (const float*)d_in[3];
    const float* b_in = (const float*)d_in[4];
    const float* A    = (const float*)d_in[5];
    const float* Bs   = (const float*)d_in[6];
    const float* C    = (const float*)d_in[7];
    const float* Wout = (const float*)d_in[8];
    const float* bo   = (const float*)d_in[9];
    float* out = (float*)d_out;

    k_pm  <<<130, 256>>>(Win, A, Bs, Wout, C, b_in);
    k_fold<<<48, 256>>>(nw, nb);
    k_ln  <<<128, 256>>>(x);
    k_scan<<<32, 512>>>();
    k_out <<<256, 256>>>(x, bo, out);
}

// round 9
// speedup vs baseline: 1.5558x; 1.1272x over previous
#include <cuda_runtime.h>
#include <math.h>

#define GRID 128
#define NT 512

// ---------------- scratch ----------------
__device__ __align__(16) float g_Ppart[16 * 32 * 1024]; // [chunk][o][d]
__device__ __align__(16) float g_MTp[4 * 16 * 1024];    // [quarter][n][d]
__device__ __align__(16) float g_PpD[1024 * 64];        // [k][{o,o} duplicated]
__device__ __align__(16) float g_MT[16 * 1024];         // [n][d]
__device__ float g_c[32];
__device__ float g_k1[32];
__device__ float g_k2[32];
__device__ __align__(16) float g_au[2 * 32 * 4096];     // [b][o][s]
__device__ __align__(16) float g_states[2 * 16 * 4096]; // [b*16+n][s]
__device__ int g_cnt;                                   // barrier (monotonic)

typedef unsigned long long ull;
__device__ __forceinline__ ull dup_f(float v) {
    ull r; asm("mov.b64 %0, {%1, %1};" : "=l"(r) : "f"(v)); return r;
}
#define FFMA2(acc, a, b) asm("fma.rn.f32x2 %0, %1, %2, %0;" : "+l"(acc) : "l"(a), "l"(b))
#define ADD2(acc, a)     asm("add.rn.f32x2 %0, %0, %1;" : "+l"(acc) : "l"(a))
__device__ __forceinline__ void unpk(float& lo, float& hi, ull v) {
    asm("mov.b64 {%0, %1}, %2;" : "=f"(lo), "=f"(hi) : "l"(v));
}
__device__ __forceinline__ void cp16(unsigned int dst, const void* src) {
    asm volatile("cp.async.ca.shared.global [%0], [%1], 16;" :: "r"(dst), "l"(src));
}

// grid-wide barrier: monotonic counter, replay-safe
__device__ __forceinline__ void gsync() {
    __syncthreads();
    if (threadIdx.x == 0) {
        __threadfence();
        int arrival = atomicAdd(&g_cnt, 1);
        int target = (arrival / GRID + 1) * GRID;
        while (*((volatile int*)&g_cnt) < target) { }
        __threadfence();
    }
    __syncthreads();
}

// ---------------- K1: prologue (unchanged from R8): P/MT split-K partials + c ----------------
__global__ void __launch_bounds__(256) k_pm(const float* __restrict__ Win,
                                            const float* __restrict__ A,
                                            const float* __restrict__ Bs,
                                            const float* __restrict__ Wout,
                                            const float* __restrict__ C,
                                            const float* __restrict__ b_in) {
    int blk = blockIdx.x;
    int tid = threadIdx.x;

    if (blk < 64) {
        __shared__ __align__(16) ull sAB2[128 * 32];
        int dt = blk >> 4;
        int chunk = blk & 15;
        int e0 = chunk * 128;
        for (int i = tid; i < 128 * 16; i += 256) {
            int el = i >> 4, n = i & 15;
            sAB2[el * 32 + n]      = dup_f(A [(e0 + el) * 16 + n]);
            sAB2[el * 32 + 16 + n] = dup_f(Bs[(e0 + el) * 16 + n]);
        }
        __syncthreads();
        int dp = tid >> 1, oh = tid & 1;
        int d = dt * 256 + dp * 2;
        ull acc[16];
#pragma unroll
        for (int o = 0; o < 16; o++) acc[o] = 0ull;
#pragma unroll 4
        for (int el = 0; el < 128; el++) {
            ull w01 = *(const ull*)(Win + (e0 + el) * 1024 + d);
            const ull* base = sAB2 + el * 32 + oh * 16;
#pragma unroll
            for (int o = 0; o < 16; o++) FFMA2(acc[o], w01, base[o]);
        }
#pragma unroll
        for (int o = 0; o < 16; o++) {
            int oi = oh * 16 + o;
            *(ull*)(g_Ppart + (chunk * 32 + oi) * 1024 + d) = acc[o];
        }
        return;
    }

    if (blk < 128) {
        __shared__ __align__(16) float sC[128 * 16];
        int mb = blk - 64;
        int tile = mb >> 2;
        int q = mb & 3;
        int row = tile * 64 + (tid >> 2);
        int nq = tid & 3;
        ull acc0 = 0ull, acc1 = 0ull;
        for (int c = 0; c < 4; c++) {
            int e0 = q * 512 + c * 128;
            __syncthreads();
            for (int i = tid; i < 512; i += 256)
                ((float4*)sC)[i] = ((const float4*)(C + e0 * 16))[i];
            __syncthreads();
            const float* wrow = Wout + row * 2048 + e0;
#pragma unroll 8
            for (int g = 0; g < 32; g++) {
                float4 w4 = *(const float4*)(wrow + g * 4);
#pragma unroll
                for (int j = 0; j < 4; j++) {
                    float wv = (j == 0) ? w4.x : (j == 1) ? w4.y : (j == 2) ? w4.z : w4.w;
                    ull wd = dup_f(wv);
                    ulonglong2 cp = *(const ulonglong2*)(sC + (g * 4 + j) * 16 + nq * 4);
                    FFMA2(acc0, wd, cp.x);
                    FFMA2(acc1, wd, cp.y);
                }
            }
        }
        float a[4];
        unpk(a[0], a[1], acc0);
        unpk(a[2], a[3], acc1);
#pragma unroll
        for (int i = 0; i < 4; i++) {
            int n = nq * 4 + i;
            g_MTp[(q * 16 + n) * 1024 + row] = a[i];
        }
        return;
    }

    {
        __shared__ float red[8 * 16];
        int lane = tid & 31, w = tid >> 5;
        const float* G = (blk == 128) ? A : Bs;
        float acc[16];
#pragma unroll
        for (int n = 0; n < 16; n++) acc[n] = 0.f;
        for (int e = tid; e < 2048; e += 256) {
            float bv = b_in[e];
            const float4* g4 = (const float4*)(G + e * 16);
            float4 c0 = g4[0], c1 = g4[1], c2 = g4[2], c3 = g4[3];
            acc[0] += bv * c0.x; acc[1] += bv * c0.y; acc[2] += bv * c0.z; acc[3] += bv * c0.w;
            acc[4] += bv * c1.x; acc[5] += bv * c1.y; acc[6] += bv * c1.z; acc[7] += bv * c1.w;
            acc[8] += bv * c2.x; acc[9] += bv * c2.y; acc[10]+= bv * c2.z; acc[11]+= bv * c2.w;
            acc[12]+= bv * c3.x; acc[13]+= bv * c3.y; acc[14]+= bv * c3.z; acc[15]+= bv * c3.w;
        }
#pragma unroll
        for (int off = 16; off; off >>= 1)
#pragma unroll
            for (int n = 0; n < 16; n++) acc[n] += __shfl_down_sync(0xffffffffu, acc[n], off);
        if (lane == 0) {
#pragma unroll
            for (int n = 0; n < 16; n++) red[w * 16 + n] = acc[n];
        }
        __syncthreads();
        if (tid < 16) {
            float s = 0.f;
#pragma unroll
            for (int j = 0; j < 8; j++) s += red[j * 16 + tid];
            if (blk == 128) g_c[tid] = s; else g_c[16 + tid] = s;
        }
    }
}

// ---------------- K2: persistent fused kernel: fold -> LN -> scan -> out ----------------
__global__ void __launch_bounds__(NT) k_main(const float* __restrict__ x,
                                             const float* __restrict__ nw,
                                             const float* __restrict__ nb,
                                             const float* __restrict__ bo,
                                             float* __restrict__ out) {
    extern __shared__ float dsm[];   // 16896 floats = 67584 B
    int tid = threadIdx.x;
    int blk = blockIdx.x;
    int lane = tid & 31, wid = tid >> 5;

    // ================= P0: fold =================
    if (blk < 32) {
        __shared__ float sred[32];
        int o = blk;
        float s1 = 0.f, s2 = 0.f;
#pragma unroll
        for (int h = 0; h < 2; h++) {
            int d = tid + h * 512;
            float p = 0.f;
#pragma unroll
            for (int c = 0; c < 16; c++) p += g_Ppart[(c * 32 + o) * 1024 + d];
            float pp = nw[d] * p;
            s1 += pp;
            s2 += nb[d] * p;
            *(float2*)&g_PpD[d * 64 + o * 2] = make_float2(pp, pp);
        }
#pragma unroll
        for (int off = 16; off; off >>= 1) {
            s1 += __shfl_down_sync(0xffffffffu, s1, off);
            s2 += __shfl_down_sync(0xffffffffu, s2, off);
        }
        if (lane == 0) { sred[wid] = s1; sred[16 + wid] = s2; }
        __syncthreads();
        if (tid == 0) {
            float S1 = 0.f, S2 = 0.f;
#pragma unroll
            for (int j = 0; j < 16; j++) { S1 += sred[j]; S2 += sred[16 + j]; }
            g_k1[o] = S1;
            g_k2[o] = S2 + g_c[o];
        }
    } else if (blk < 64) {
        int base = (blk - 32) * 512 + tid;
        int d = base & 1023, n = base >> 10;
        float s = 0.f;
#pragma unroll
        for (int q = 0; q < 4; q++) s += g_MTp[(q * 16 + n) * 1024 + d];
        g_MT[n * 1024 + d] = s;
    }
    gsync();

    // ================= P1: LN + projection =================
    {
        float* sXT = dsm;          // 2 x (64 k x 68) = 8704 floats
        float* sPD = dsm + 8704;   // 2 x (64 k x 64) = 8192 floats
        int tg = tid & 15;         // token quad: tokens tg*4..+3
        int ks = (tid >> 4) & 3;   // k-split within chunk
        int og = tid >> 6;         // output quad (warp-uniform)
        int T0 = blk * 64;

        unsigned spdb = (unsigned)__cvta_generic_to_shared(sPD);

        float xa[2][4];
        // prologue: chunk 0
#pragma unroll
        for (int it = 0; it < 2; it++) {
            int slot = tid + it * 512;
            int row = slot >> 4, col = slot & 15;
            cp16(spdb + (row * 64 + col * 4) * 4, g_PpD + row * 64 + col * 4);
        }
        asm volatile("cp.async.commit_group;");
#pragma unroll
        for (int it = 0; it < 2; it++) {
            int slot = tid + it * 512;
            int k = slot & 63, tq = slot >> 6;
            const float* src = x + (T0 + tq * 4) * 1024 + k;
            *(float4*)&sXT[k * 68 + tq * 4] = make_float4(src[0], src[1024], src[2048], src[3072]);
        }
        asm volatile("cp.async.wait_group 0;");
        __syncthreads();

        ull a01[4] = {0,0,0,0}, a23[4] = {0,0,0,0};
        ull s101 = 0, s123 = 0, s201 = 0, s223 = 0;

        for (int c = 0; c < 16; c++) {
            int buf = c & 1;
            if (c < 15) {
#pragma unroll
                for (int it = 0; it < 2; it++) {
                    int slot = tid + it * 512;
                    int row = slot >> 4, col = slot & 15;
                    cp16(spdb + ((buf ^ 1) * 4096 + row * 64 + col * 4) * 4,
                         g_PpD + ((c + 1) * 64 + row) * 64 + col * 4);
                }
                asm volatile("cp.async.commit_group;");
#pragma unroll
                for (int it = 0; it < 2; it++) {
                    int slot = tid + it * 512;
                    int k = slot & 63, tq = slot >> 6;
                    const float* src = x + (T0 + tq * 4) * 1024 + (c + 1) * 64 + k;
                    xa[it][0] = src[0]; xa[it][1] = src[1024];
                    xa[it][2] = src[2048]; xa[it][3] = src[3072];
                }
            }
            const float* xb = sXT + buf * 4352 + tg * 4;
            const float* pb = sPD + buf * 4096 + og * 8;
#pragma unroll
            for (int kl = 0; kl < 16; kl++) {
                int k = ks * 16 + kl;
                ulonglong2 xx = *(const ulonglong2*)(xb + k * 68);
                ulonglong2 q0 = *(const ulonglong2*)(pb + k * 64);
                ulonglong2 q1 = *(const ulonglong2*)(pb + k * 64 + 4);
                FFMA2(a01[0], xx.x, q0.x); FFMA2(a23[0], xx.y, q0.x);
                FFMA2(a01[1], xx.x, q0.y); FFMA2(a23[1], xx.y, q0.y);
                FFMA2(a01[2], xx.x, q1.x); FFMA2(a23[2], xx.y, q1.x);
                FFMA2(a01[3], xx.x, q1.y); FFMA2(a23[3], xx.y, q1.y);
                if (og == 0) {   // warp-uniform: only 2 warps pay for stats
                    ADD2(s101, xx.x); ADD2(s123, xx.y);
                    FFMA2(s201, xx.x, xx.x); FFMA2(s223, xx.y, xx.y);
                }
            }
            if (c < 15) {
#pragma unroll
                for (int it = 0; it < 2; it++) {
                    int slot = tid + it * 512;
                    int k = slot & 63, tq = slot >> 6;
                    *(float4*)&sXT[(buf ^ 1) * 4352 + k * 68 + tq * 4] =
                        make_float4(xa[it][0], xa[it][1], xa[it][2], xa[it][3]);
                }
                asm volatile("cp.async.wait_group 0;");
            }
            __syncthreads();
        }

        // ---- combine k-splits + stats + epilogue ----
        float* A  = dsm;           // 512 slots x 16 floats
        float* B  = dsm + 8192;    // 64 slots x 8 floats
        float* Cc = dsm + 8704;    // mu[64], rs[64]
        if (ks > 0) {
            ull* d8 = (ull*)&A[tid * 16];
#pragma unroll
            for (int i = 0; i < 4; i++) { d8[i] = a01[i]; d8[4 + i] = a23[i]; }
        }
        if (og == 0) {
            ull* sb = (ull*)&B[(ks * 16 + tg) * 8];
            sb[0] = s101; sb[1] = s123; sb[2] = s201; sb[3] = s223;
        }
        __syncthreads();
        if (tid < 64) {
            int tq = tid >> 2, j = tid & 3;
            float s1 = 0.f, s2 = 0.f;
#pragma unroll
            for (int k2 = 0; k2 < 4; k2++) {
                const float* bb = &B[(k2 * 16 + tq) * 8];
                s1 += bb[j];
                s2 += bb[4 + j];
            }
            float mu = s1 * (1.f / 1024.f);
            float var = s2 * (1.f / 1024.f) - mu * mu;
            Cc[tid] = mu;
            Cc[64 + tid] = rsqrtf(var + 1e-5f);
        }
        if (ks == 0) {
#pragma unroll
            for (int k2 = 1; k2 < 4; k2++) {
                const ull* src = (const ull*)&A[(tid + k2 * 16) * 16];
#pragma unroll
                for (int i = 0; i < 4; i++) { ADD2(a01[i], src[i]); ADD2(a23[i], src[4 + i]); }
            }
        }
        __syncthreads();
        if (ks == 0) {
            float mu[4], rs[4];
#pragma unroll
            for (int j = 0; j < 4; j++) { mu[j] = Cc[tg * 4 + j]; rs[j] = Cc[64 + tg * 4 + j]; }
            int b = T0 >> 12;
            int s0 = (T0 & 4095) + tg * 4;
#pragma unroll
            for (int i = 0; i < 4; i++) {
                int o = og * 4 + i;
                float k1v = g_k1[o], k2v = g_k2[o];
                float v[4];
                unpk(v[0], v[1], a01[i]);
                unpk(v[2], v[3], a23[i]);
#pragma unroll
                for (int j = 0; j < 4; j++) {
                    v[j] = rs[j] * v[j] - mu[j] * rs[j] * k1v + k2v;
                    if (o < 16) v[j] = 1.f / (1.f + __expf(-v[j]));
                }
                *(float4*)&g_au[(b * 32 + o) * 4096 + s0] = make_float4(v[0], v[1], v[2], v[3]);
            }
        }
    }
    gsync();

    // ================= P2: scan (blocks 0..31) =================
    if (blk < 32) {
        __shared__ float wA[16], wU[16], pU[16];
        int bn = blk;
        int b = bn >> 4, n = bn & 15;
        const float* ap = g_au + (b * 32 + n) * 4096;
        const float* up = g_au + (b * 32 + 16 + n) * 4096;

        float a[8], u[8];
        const float4* a4 = (const float4*)(ap + tid * 8);
        const float4* u4 = (const float4*)(up + tid * 8);
#pragma unroll
        for (int q = 0; q < 2; q++) {
            float4 av = a4[q], uv = u4[q];
            a[q*4+0] = av.x; a[q*4+1] = av.y; a[q*4+2] = av.z; a[q*4+3] = av.w;
            u[q*4+0] = uv.x; u[q*4+1] = uv.y; u[q*4+2] = uv.z; u[q*4+3] = uv.w;
        }
        float Aloc = 1.f, Uloc = 0.f;
#pragma unroll
        for (int i = 0; i < 8; i++) { Uloc = Uloc * a[i] + u[i]; Aloc *= a[i]; }

        float Ai = Aloc, Ui = Uloc;
#pragma unroll
        for (int off = 1; off < 32; off <<= 1) {
            float Ap = __shfl_up_sync(0xffffffffu, Ai, off);
            float Up = __shfl_up_sync(0xffffffffu, Ui, off);
            if (lane >= off) { Ui = Up * Ai + Ui; Ai = Ap * Ai; }
        }
        if (lane == 31) { wA[wid] = Ai; wU[wid] = Ui; }
        __syncthreads();
        if (tid == 0) {
            float Uc = 0.f;
#pragma unroll
            for (int j = 0; j < 16; j++) {
                pU[j] = Uc;
                Uc = Uc * wA[j] + wU[j];
            }
        }
        __syncthreads();
        float eA = __shfl_up_sync(0xffffffffu, Ai, 1);
        float eU = __shfl_up_sync(0xffffffffu, Ui, 1);
        if (lane == 0) { eA = 1.f; eU = 0.f; }
        float s = pU[wid] * eA + eU;

        float o8[8];
#pragma unroll
        for (int i = 0; i < 8; i++) { s = a[i] * s + u[i]; o8[i] = s; }
        float4* dst = (float4*)(g_states + bn * 4096 + tid * 8);
#pragma unroll
        for (int q = 0; q < 2; q++)
            dst[q] = make_float4(o8[q*4+0], o8[q*4+1], o8[q*4+2], o8[q*4+3]);
    }
    gsync();

    // ================= P3: out =================
    {
        float* sST = dsm;   // 64 tokens x 17
        int T0 = blk * 64;
        int b = T0 >> 12, s0 = T0 & 4095;
#pragma unroll
        for (int it = 0; it < 2; it++) {
            int idx = tid + it * 512;
            int soff = idx & 63, n = idx >> 6;
            sST[soff * 17 + n] = g_states[(b * 16 + n) * 4096 + s0 + soff];
        }
        int dq = tid & 255;
        int th = tid >> 8;
        ull m01[16], m23[16];
#pragma unroll
        for (int n = 0; n < 16; n++) {
            ulonglong2 mm = *(const ulonglong2*)(g_MT + n * 1024 + dq * 4);
            m01[n] = mm.x; m23[n] = mm.y;
        }
        ulonglong2 bov = *(const ulonglong2*)(bo + dq * 4);
        __syncthreads();

        for (int tl = 0; tl < 32; tl++) {
            int t = th * 32 + tl;
            ulonglong2 xv = *(const ulonglong2*)(x + (T0 + t) * 1024 + dq * 4);
            ull r01, r23;
            asm("add.rn.f32x2 %0, %1, %2;" : "=l"(r01) : "l"(xv.x), "l"(bov.x));
            asm("add.rn.f32x2 %0, %1, %2;" : "=l"(r23) : "l"(xv.y), "l"(bov.y));
#pragma unroll
            for (int n = 0; n < 16; n++) {
                ull sv = dup_f(sST[t * 17 + n]);
                FFMA2(r01, sv, m01[n]);
                FFMA2(r23, sv, m23[n]);
            }
            ulonglong2 res; res.x = r01; res.y = r23;
            *(ulonglong2*)(out + (T0 + t) * 1024 + dq * 4) = res;
        }
    }
}

// ---------------- launch ----------------
extern "C" void kernel_launch(void* const* d_in, const int* in_sizes, int n_in,
                              void* d_out, int out_size) {
    const float* x    = (const float*)d_in[0];
    const float* nw   = (const float*)d_in[1];
    const float* nb   = (const float*)d_in[2];
    const float* Win  = (const float*)d_in[3];
    const float* b_in = (const float*)d_in[4];
    const float* A    = (const float*)d_in[5];
    const float* Bs   = (const float*)d_in[6];
    const float* C    = (const float*)d_in[7];
    const float* Wout = (const float*)d_in[8];
    const float* bo   = (const float*)d_in[9];
    float* out = (float*)d_out;

    cudaFuncSetAttribute(k_main, cudaFuncAttributeMaxDynamicSharedMemorySize, 69632);

    k_pm  <<<130, 256>>>(Win, A, Bs, Wout, C, b_in);
    k_main<<<GRID, NT, 67584>>>(x, nw, nb, bo, out);
}